// round 1
// baseline (speedup 1.0000x reference)
#include <cuda_runtime.h>
#include <stdint.h>

// Problem constants (match reference_code)
static constexpr int L     = 4096;  // MAXLEN (seq dim and feature dim)
static constexpr int LIMIT = 256;   // band width
static constexpr int BATCH = 4;

// out[b, i, j] = x[b, i, i + j]  if i + j < L else 0,  j in [0, LIMIT)
//
// For a fixed (b, i) the source elements are CONTIGUOUS: x_row[i .. i+255].
// So this is a shifted row copy with a tail predicate. We map 4 consecutive
// j's to one thread: coalesced scalar loads (row base is only 4B-aligned
// since it starts at element i), one aligned float4 store.
__global__ __launch_bounds__(256) void band_gather_kernel(
    const float* __restrict__ x, float4* __restrict__ out)
{
    // tid indexes output in float4 units: (B*L) rows * (LIMIT/4) quads
    int tid = blockIdx.x * blockDim.x + threadIdx.x;

    int q   = tid & (LIMIT / 4 - 1);   // quad index within row: 0..63
    int row = tid >> 6;                // b*L + i
    int i   = row & (L - 1);           // row within batch
    int j   = q << 2;                  // first j of this quad

    const float* src = x + (size_t)row * L + i + j;
    int rem = L - i - j;               // how many of the 4 are in-bounds

    float4 v;
    v.x = (rem > 0) ? src[0] : 0.0f;
    v.y = (rem > 1) ? src[1] : 0.0f;
    v.z = (rem > 2) ? src[2] : 0.0f;
    v.w = (rem > 3) ? src[3] : 0.0f;

    out[tid] = v;
}

extern "C" void kernel_launch(void* const* d_in, const int* in_sizes, int n_in,
                              void* d_out, int out_size)
{
    const float* x = (const float*)d_in[0];
    float4* out = (float4*)d_out;

    // total float4 elements = BATCH * L * LIMIT / 4 = 1,048,576
    int total_quads = BATCH * L * (LIMIT / 4);
    int threads = 256;
    int blocks  = total_quads / threads;  // 4096

    band_gather_kernel<<<blocks, threads>>>(x, out);
}

// round 2
// speedup vs baseline: 1.0323x; 1.0323x over previous
#include <cuda_runtime.h>
#include <stdint.h>

// Problem constants (match reference_code)
static constexpr int L     = 4096;  // MAXLEN
static constexpr int LIMIT = 256;   // band width
static constexpr int BATCH = 4;
static constexpr int QUADS_PER_ROW = LIMIT / 4;      // 64
static constexpr int TOTAL_QUADS   = BATCH * L * QUADS_PER_ROW; // 1,048,576
static constexpr int ITEMS = 4;                      // quads per thread (MLP booster)

// out[b, i, j] = x[b, i, i + j]  if i + j < L else 0
// Shifted row copy. Each thread handles ITEMS=4 quads, strided by blockDim
// so loads/stores stay coalesced; all 16 loads are independent and get
// front-batched by ptxas -> MLP=16 per thread, hiding DRAM latency.
__global__ __launch_bounds__(256) void band_gather_kernel(
    const float* __restrict__ x, float4* __restrict__ out)
{
    int base = blockIdx.x * (blockDim.x * ITEMS) + threadIdx.x;

    float4 v[ITEMS];

    #pragma unroll
    for (int k = 0; k < ITEMS; k++) {
        int tid = base + k * 256;          // quad index
        int q   = tid & (QUADS_PER_ROW - 1);
        int row = tid >> 6;                // b*L + i
        int i   = row & (L - 1);
        int j   = q << 2;

        const float* src = x + (size_t)row * L + i + j;
        int rem = L - i - j;

        v[k].x = (rem > 0) ? src[0] : 0.0f;
        v[k].y = (rem > 1) ? src[1] : 0.0f;
        v[k].z = (rem > 2) ? src[2] : 0.0f;
        v[k].w = (rem > 3) ? src[3] : 0.0f;
    }

    #pragma unroll
    for (int k = 0; k < ITEMS; k++) {
        out[base + k * 256] = v[k];
    }
}

extern "C" void kernel_launch(void* const* d_in, const int* in_sizes, int n_in,
                              void* d_out, int out_size)
{
    const float* x = (const float*)d_in[0];
    float4* out = (float4*)d_out;

    int threads = 256;
    int blocks  = TOTAL_QUADS / (threads * ITEMS);   // 1024

    band_gather_kernel<<<blocks, threads>>>(x, out);
}